// round 4
// baseline (speedup 1.0000x reference)
#include <cuda_runtime.h>
#include <math.h>

#define BATCH 4096
#define DIM   128
#define KNBR  200
#define NCLS  1000
#define GC    0.5f          // 1/(2*sigma^2), sigma=1
#define THREADS 256
#define WARPS   (THREADS/32)
#define PER_WARP (KNBR/WARPS)   // 25

#define N_CENTRES_ELEMS 12800000
#define N_FEAT_ELEMS    524288
#define N_NBR_ELEMS     819200
#define N_100K          100000

#define FLT_MIN_NORMAL 1.17549435082228750797e-38f   // 2^-126

// Emulate aarch64 FPCR.FZ semantics: any op result that is subnormal flushes to 0.
__device__ __forceinline__ float ftz(float v) {
    return (v < FLT_MIN_NORMAL) ? 0.0f : v;   // v >= 0 in all our uses
}

__global__ __launch_bounds__(THREADS, 8)
void gaussian_kernels_kernel(const float* __restrict__ features,
                             const float* __restrict__ centres,
                             const void*  __restrict__ cand0,   // weight OR centre_labels
                             const void*  __restrict__ cand1,   // the other one
                             const int*   __restrict__ neighbours,
                             float*       __restrict__ out)
{
    __shared__ float p[NCLS];
    __shared__ float warp_sums[WARPS];

    const int b    = blockIdx.x;
    const int tid  = threadIdx.x;
    const int lane = tid & 31;
    const int warp = tid >> 5;

    // ---- disambiguate weight vs centre_labels by bit pattern (deterministic) ----
    const unsigned int* a0 = (const unsigned int*)cand0;
    const bool first_is_labels =
        (a0[0] < 1000u) && (a0[1] < 1000u) && (a0[2] < 1000u) && (a0[3] < 1000u);
    const float* weight        = first_is_labels ? (const float*)cand1 : (const float*)cand0;
    const int*   centre_labels = first_is_labels ? (const int*)cand0   : (const int*)cand1;

    // zero the class histogram
    #pragma unroll
    for (int i = tid; i < NCLS; i += THREADS) p[i] = 0.0f;

    // each lane holds 4 contiguous dims of this row's feature vector
    const float4 f = reinterpret_cast<const float4*>(features + (size_t)b * DIM)[lane];

    __syncthreads();

    const int* nb = neighbours + (size_t)b * KNBR;

    // each warp handles 25 neighbours
    #pragma unroll 5
    for (int i = 0; i < PER_WARP; i++) {
        const int k = warp * PER_WARP + i;
        const int n = nb[k];                       // uniform across the warp
        const float4 c = reinterpret_cast<const float4*>(centres + (size_t)n * DIM)[lane];
        const float dx = f.x - c.x;
        const float dy = f.y - c.y;
        const float dz = f.z - c.z;
        const float dw = f.w - c.w;
        float s = dx*dx + dy*dy + dz*dz + dw*dw;
        // butterfly reduce across the warp -> full squared distance on every lane
        s += __shfl_xor_sync(0xffffffffu, s, 16);
        s += __shfl_xor_sync(0xffffffffu, s, 8);
        s += __shfl_xor_sync(0xffffffffu, s, 4);
        s += __shfl_xor_sync(0xffffffffu, s, 2);
        s += __shfl_xor_sync(0xffffffffu, s, 1);
        if (lane == 0) {
            const float w   = weight[n];
            const int   lbl = centre_labels[n];
            // reference semantics (aarch64 FZ): every op's subnormal result flushes to 0
            const float e1   = ftz(expf(-s * GC));   // exp(-d * GC)
            const float e2   = expf(w);              // ~[0.9, 1.1], always normal
            const float kern = ftz(e1 * e2);         // product may underflow -> flush
            if (kern != 0.0f) atomicAdd(&p[lbl], kern);
        }
    }

    __syncthreads();

    // epsilon-clamp empty bins and accumulate the row sum
    float local = 0.0f;
    #pragma unroll
    for (int i = tid; i < NCLS; i += THREADS) {
        float v = p[i];
        v = (v == 0.0f) ? 1e-10f : v;
        p[i] = v;
        local += v;
    }
    // warp reduce
    local += __shfl_xor_sync(0xffffffffu, local, 16);
    local += __shfl_xor_sync(0xffffffffu, local, 8);
    local += __shfl_xor_sync(0xffffffffu, local, 4);
    local += __shfl_xor_sync(0xffffffffu, local, 2);
    local += __shfl_xor_sync(0xffffffffu, local, 1);
    if (lane == 0) warp_sums[warp] = local;
    __syncthreads();

    float total = 0.0f;
    #pragma unroll
    for (int w = 0; w < WARPS; w++) total += warp_sums[w];

    // write log(p / sum)
    float* orow = out + (size_t)b * NCLS;
    #pragma unroll
    for (int i = tid; i < NCLS; i += THREADS) {
        orow[i] = logf(p[i] / total);
    }
}

extern "C" void kernel_launch(void* const* d_in, const int* in_sizes, int n_in,
                              void* d_out, int out_size)
{
    // Identify inputs by element count (ordering-agnostic).
    const float* features   = nullptr;
    const float* centres    = nullptr;
    const int*   neighbours = nullptr;
    const void*  c100[2]    = {nullptr, nullptr};
    int n100 = 0;

    for (int i = 0; i < n_in; i++) {
        switch (in_sizes[i]) {
            case N_CENTRES_ELEMS: centres    = (const float*)d_in[i]; break;
            case N_FEAT_ELEMS:    features   = (const float*)d_in[i]; break;
            case N_NBR_ELEMS:     neighbours = (const int*)  d_in[i]; break;
            case N_100K:          if (n100 < 2) c100[n100++] = d_in[i]; break;
            default: break;
        }
    }

    float* out = (float*)d_out;
    gaussian_kernels_kernel<<<BATCH, THREADS>>>(features, centres,
                                                c100[0], c100[1],
                                                neighbours, out);
}